// round 15
// baseline (speedup 1.0000x reference)
#include <cuda_runtime.h>
#include <cuda_bf16.h>
#include <math.h>
#include <stdint.h>

#define BB 32
#define HH 1024
#define EE 512
#define VV 32001
#define NSTEP 32
#define NT 251            // projection tiles of 128 vocab rows
#define KSPL 4            // k-split for gate GEMMs

// ---------------- device state ----------------
__device__ __align__(16) uint8_t d_whiB[NT * 16 * 16384];  // w_out bf16 hi, blocked+swizzled
__device__ __align__(16) uint8_t d_wloB[NT * 16 * 16384];  // w_out bf16 lo
__device__ __align__(16) uint8_t d_g0hi[32 * 24 * 16384];  // layer0 gate w bf16 hi
__device__ __align__(16) uint8_t d_g0lo[32 * 24 * 16384];
__device__ __align__(16) uint8_t d_g1hi[32 * 32 * 16384];  // layer1 gate w bf16 hi
__device__ __align__(16) uint8_t d_g1lo[32 * 32 * 16384];
__device__ __align__(16) uint8_t d_hchi[2][2][16 * 4096];  // h bf16 hi [parity][layer]
__device__ __align__(16) uint8_t d_hclo[2][2][16 * 4096];
__device__ __align__(16) uint8_t d_xehi[8 * 4096];         // embedded x bf16 hi
__device__ __align__(16) uint8_t d_xelo[8 * 4096];
__device__ float d_cst[2 * HH * BB];     // cell state [layer][j][b]
__device__ float d_gp[KSPL * 4096 * BB]; // gate GEMM partials [split][col][b]
__device__ float d_pmax[NT * BB];
__device__ int   d_pidx[NT * BB];
__device__ int   d_tok[BB];
__device__ int   d_run[BB];
__device__ int   d_len[BB];
__device__ int   d_cntg[2][32];          // per-layer per-tile completion counters (zero-init)
__device__ int   d_cntp;                 // projection completion counter (zero-init)

__device__ __forceinline__ void cpa16(uint32_t d, const void* s) {
    asm volatile("cp.async.cg.shared.global [%0], [%1], 16;" :: "r"(d), "l"(s));
}
__device__ __forceinline__ void cpcommit() { asm volatile("cp.async.commit_group;"); }
__device__ __forceinline__ void cpwait2() { asm volatile("cp.async.wait_group 2;"); }
__device__ __forceinline__ uint32_t sw128(uint32_t off) { return off ^ ((off >> 3) & 0x70); }

__device__ __forceinline__ void ldsm4(uint32_t* r, uint32_t a) {
    asm volatile("ldmatrix.sync.aligned.m8n8.x4.shared.b16 {%0,%1,%2,%3},[%4];"
                 : "=r"(r[0]), "=r"(r[1]), "=r"(r[2]), "=r"(r[3]) : "r"(a));
}
__device__ __forceinline__ void mma16816(float* c, const uint32_t* a, uint32_t b0, uint32_t b1) {
    asm volatile(
        "mma.sync.aligned.m16n8k16.row.col.f32.bf16.bf16.f32 "
        "{%0,%1,%2,%3},{%4,%5,%6,%7},{%8,%9},{%0,%1,%2,%3};"
        : "+f"(c[0]), "+f"(c[1]), "+f"(c[2]), "+f"(c[3])
        : "r"(a[0]), "r"(a[1]), "r"(a[2]), "r"(a[3]), "r"(b0), "r"(b1));
}
__device__ __forceinline__ void export_h(uint8_t* dhi, uint8_t* dlo, int unit, int b, float v) {
    uint32_t off = (unit >> 6) * 4096 + sw128((uint32_t)((b << 7) + ((unit & 63) << 1)));
    __nv_bfloat16 hi = __float2bfloat16(v);
    *(__nv_bfloat16*)(dhi + off) = hi;
    *(__nv_bfloat16*)(dlo + off) = __float2bfloat16(v - __bfloat162float(hi));
}

// ---------------- prep A: state init + initial h bf16 export ----------------
__global__ void __launch_bounds__(256) k_prep(const float* __restrict__ h0,
                                              const float* __restrict__ c0) {
    int i = blockIdx.x * 256 + threadIdx.x;   // < 65536
    int l = i >> 15; int r = i & 32767; int b = r >> 10; int j = r & 1023;
    float hv = h0[i];
    d_cst[(l * 1024 + j) * 32 + b] = c0[i];
    export_h(d_hchi[0][l], d_hclo[0][l], j, b, hv);
    if (i < 32) { d_tok[i] = 32000; d_run[i] = 1; d_len[i] = 0; }
}

// ---------------- prep B: w_out -> bf16 hi/lo, blocked + SW128-swizzled ----------------
__global__ void __launch_bounds__(256) k_prepw(const float* __restrict__ wout) {
    __shared__ __align__(16) uint8_t hbuf[16384];
    __shared__ __align__(16) uint8_t lbuf[16384];
    int chunk = blockIdx.x, tile = blockIdx.y, t = threadIdx.x;
#pragma unroll 4
    for (int i = 0; i < 32; i++) {
        int lin = i * 256 + t;            // 0..8191
        int m = lin >> 6, k = lin & 63;
        int gm = tile * 128 + m;
        float v = (gm < VV) ? wout[(size_t)gm * 1024 + chunk * 64 + k] : 0.f;
        __nv_bfloat16 hi = __float2bfloat16(v);
        __nv_bfloat16 lo = __float2bfloat16(v - __bfloat162float(hi));
        uint32_t off = sw128((uint32_t)(m * 128 + k * 2));
        *(__nv_bfloat16*)(hbuf + off) = hi;
        *(__nv_bfloat16*)(lbuf + off) = lo;
    }
    __syncthreads();
    size_t base = ((size_t)tile * 16 + chunk) * 16384;
#pragma unroll
    for (int q = 0; q < 4; q++) {
        int idx = t + 256 * q;
        ((float4*)(d_whiB + base))[idx] = ((const float4*)hbuf)[idx];
        ((float4*)(d_wloB + base))[idx] = ((const float4*)lbuf)[idx];
    }
}

// ---------------- prep C: gate weights -> bf16 hi/lo blocked tiles ----------------
__global__ void __launch_bounds__(256) k_prepg(const float* __restrict__ wih0,
                                               const float* __restrict__ whh0,
                                               const float* __restrict__ wih1,
                                               const float* __restrict__ whh1) {
    __shared__ __align__(16) uint8_t hbuf[16384];
    __shared__ __align__(16) uint8_t lbuf[16384];
    int chunk = blockIdx.x, tile = blockIdx.y, layer = blockIdx.z, t = threadIdx.x;
    if (!layer && chunk >= 24) return;
    const float* wa = layer ? wih1 : wih0;
    const float* wb = layer ? whh1 : whh0;
    int Ka = layer ? 1024 : 512;
    int NCH = layer ? 32 : 24;
#pragma unroll 4
    for (int i = 0; i < 32; i++) {
        int lin = i * 256 + t;
        int m = lin >> 6, k = lin & 63;
        int kg = chunk * 64 + k;
        int cp = tile * 128 + m;
        int unit = (cp >> 5) * 8 + ((cp >> 2) & 7);
        int gg = cp & 3;
        int row = gg * 1024 + unit;
        float v = (kg < Ka) ? wa[(size_t)row * Ka + kg] : wb[(size_t)row * 1024 + (kg - Ka)];
        __nv_bfloat16 hi = __float2bfloat16(v);
        __nv_bfloat16 lo = __float2bfloat16(v - __bfloat162float(hi));
        uint32_t off = sw128((uint32_t)(m * 128 + k * 2));
        *(__nv_bfloat16*)(hbuf + off) = hi;
        *(__nv_bfloat16*)(lbuf + off) = lo;
    }
    __syncthreads();
    uint8_t* oh = layer ? d_g1hi : d_g0hi;
    uint8_t* ol = layer ? d_g1lo : d_g0lo;
    size_t base = ((size_t)tile * NCH + chunk) * 16384;
#pragma unroll
    for (int q = 0; q < 4; q++) {
        int idx = t + 256 * q;
        ((float4*)(oh + base))[idx] = ((const float4*)hbuf)[idx];
        ((float4*)(ol + base))[idx] = ((const float4*)lbuf)[idx];
    }
}

// ---------------- initial SOS embedding ----------------
__global__ void __launch_bounds__(512) k_embed0(const float* __restrict__ emb) {
    int b = blockIdx.x, t = threadIdx.x;       // t = 0..511 == EE
    float v = emb[(size_t)d_tok[b] * EE + t];
    uint32_t off = (t >> 6) * 4096 + sw128((uint32_t)((b << 7) + ((t & 63) << 1)));
    __nv_bfloat16 hi = __float2bfloat16(v);
    *(__nv_bfloat16*)(&d_xehi[off]) = hi;
    *(__nv_bfloat16*)(&d_xelo[off]) = __float2bfloat16(v - __bfloat162float(hi));
}

// ---------------- gate GEMM (mma.sync) + fused LSTM update in last split-block ----------------
// grid (32 tiles, KSPL splits), 256 threads; dyn smem 163840 = 4 slots x 40KB
__global__ void __launch_bounds__(256) k_gmm(int layer, int parity,
                                             const float* __restrict__ bih,
                                             const float* __restrict__ bhh) {
    extern __shared__ __align__(16) uint8_t dsm[];
    uint32_t dbase = (uint32_t)__cvta_generic_to_shared(dsm);
    int t = threadIdx.x;
    int w = t >> 5, lane = t & 31;
    int tile = blockIdx.x, split = blockIdx.y;
    const uint8_t* whi = layer ? d_g1hi : d_g0hi;
    const uint8_t* wlo = layer ? d_g1lo : d_g0lo;
    int NCH = layer ? 32 : 24;
    int Q = NCH >> 2;                 // 8 or 6 chunks per split

    auto xhi = [&](int c) -> const uint8_t* {
        if (layer) return (c < 16) ? &d_hchi[1 - parity][0][c * 4096]
                                   : &d_hchi[parity][1][(c - 16) * 4096];
        return (c < 8) ? &d_xehi[c * 4096] : &d_hchi[parity][0][(c - 8) * 4096];
    };
    auto xlo = [&](int c) -> const uint8_t* {
        if (layer) return (c < 16) ? &d_hclo[1 - parity][0][c * 4096]
                                   : &d_hclo[parity][1][(c - 16) * 4096];
        return (c < 8) ? &d_xelo[c * 4096] : &d_hclo[parity][0][(c - 8) * 4096];
    };

    auto prefetch = [&](int s) {
        int ci = split * Q + s;
        uint32_t sb = dbase + (s & 3) * 40960;
        const uint8_t* wh = whi + ((size_t)tile * NCH + ci) * 16384;
        const uint8_t* wl = wlo + ((size_t)tile * NCH + ci) * 16384;
#pragma unroll
        for (int q = 0; q < 4; q++) {
            int idx = t + 256 * q;
            cpa16(sb + idx * 16, wh + idx * 16);
        }
#pragma unroll
        for (int q = 0; q < 4; q++) {
            int idx = t + 256 * q;
            cpa16(sb + 16384 + idx * 16, wl + idx * 16);
        }
        cpa16(sb + 32768 + t * 16, xhi(ci) + t * 16);
        cpa16(sb + 36864 + t * 16, xlo(ci) + t * 16);
        cpcommit();
    };
    prefetch(0); prefetch(1); prefetch(2);

    int mrowA = w * 16 + (lane & 7) + ((lane >> 3) & 1) * 8;
    int khA = (lane >> 4) & 1;
    int nrowB = ((lane >> 4) & 1) * 8 + (lane & 7);
    int khB = (lane >> 3) & 1;

    float acc[4][4];
#pragma unroll
    for (int j = 0; j < 4; j++)
#pragma unroll
        for (int q = 0; q < 4; q++) acc[j][q] = 0.f;

    for (int s = 0; s < Q; s++) {
        cpwait2();
        __syncthreads();
        uint32_t sb = dbase + (s & 3) * 40960;
#pragma unroll
        for (int kc = 0; kc < 4; kc++) {
            uint32_t offA = sw128((uint32_t)(mrowA * 128 + kc * 32 + khA * 16));
            uint32_t offB0 = sw128((uint32_t)(nrowB * 128 + kc * 32 + khB * 16));
            uint32_t offB1 = sw128((uint32_t)((nrowB + 16) * 128 + kc * 32 + khB * 16));
            uint32_t ah[4], al[4];
            uint32_t bh[8], bl[8];
            ldsm4(ah, sb + offA);
            ldsm4(al, sb + 16384 + offA);
            ldsm4(bh,     sb + 32768 + offB0);
            ldsm4(bh + 4, sb + 32768 + offB1);
            ldsm4(bl,     sb + 36864 + offB0);
            ldsm4(bl + 4, sb + 36864 + offB1);
#pragma unroll
            for (int nt = 0; nt < 4; nt++) {
                mma16816(acc[nt], ah, bh[nt * 2], bh[nt * 2 + 1]);
                mma16816(acc[nt], al, bh[nt * 2], bh[nt * 2 + 1]);
                mma16816(acc[nt], ah, bl[nt * 2], bl[nt * 2 + 1]);
            }
        }
        __syncthreads();
        if (s + 3 < Q) prefetch(s + 3); else cpcommit();
    }

    // fragments -> smem, fp32 partial store
    float* sv = (float*)dsm;
    __syncthreads();
    int r0 = w * 16 + (lane >> 2);
    int c0 = 2 * (lane & 3);
#pragma unroll
    for (int nt = 0; nt < 4; nt++) {
        int c = nt * 8 + c0;
        sv[r0 * 33 + c]           = acc[nt][0];
        sv[r0 * 33 + c + 1]       = acc[nt][1];
        sv[(r0 + 8) * 33 + c]     = acc[nt][2];
        sv[(r0 + 8) * 33 + c + 1] = acc[nt][3];
    }
    __syncthreads();

    int row = t >> 1;
    int chalf = (t & 1) * 16;
    size_t base = ((size_t)split * 4096 + tile * 128 + row) * 32 + chalf;
#pragma unroll
    for (int cc = 0; cc < 16; cc++)
        d_gp[base + cc] = sv[row * 33 + chalf + cc];

    // ---- last split-block for this tile performs the LSTM update ----
    __threadfence();
    __syncthreads();
    __shared__ int lastf;
    if (t == 0) lastf = (atomicAdd(&d_cntg[layer][tile], 1) == KSPL - 1) ? 1 : 0;
    __syncthreads();
    if (!lastf) return;
    if (t == 0) d_cntg[layer][tile] = 0;
    __threadfence();

    uint8_t* ohi = d_hchi[1 - parity][layer];
    uint8_t* olo = d_hclo[1 - parity][layer];
    for (int i = t; i < 1024; i += 256) {
        int lu = i >> 5, b = i & 31;
        int unit = tile * 32 + lu;
        int col = tile * 128 + (lu >> 3) * 32 + (lu & 7) * 4;
        float a[4];
#pragma unroll
        for (int q = 0; q < 4; q++) a[q] = bih[q * 1024 + unit] + bhh[q * 1024 + unit];
#pragma unroll
        for (int ks = 0; ks < KSPL; ks++)
#pragma unroll
            for (int q = 0; q < 4; q++)
                a[q] += d_gp[((size_t)ks * 4096 + col + q) * 32 + b];
        int ci = (layer * HH + unit) * 32 + b;
        float c = d_cst[ci];
        float ig = 1.f / (1.f + expf(-a[0]));
        float fg = 1.f / (1.f + expf(-a[1]));
        float gt = tanhf(a[2]);
        float og = 1.f / (1.f + expf(-a[3]));
        float c2 = fg * c + ig * gt;
        d_cst[ci] = c2;
        export_h(ohi, olo, unit, b, og * tanhf(c2));
    }
}

// ---------------- tensor-core projection + fused select/embed in last block ----------------
// grid NT, 256 threads; dyn smem 163840 = 4 slots x 40KB
__global__ void __launch_bounds__(256) k_projMM(const float* __restrict__ bias,
                                                float* __restrict__ outp, int s_step,
                                                int parity, const float* __restrict__ emb,
                                                int has_len) {
    extern __shared__ __align__(16) uint8_t dsm[];
    uint32_t dbase = (uint32_t)__cvta_generic_to_shared(dsm);
    int t = threadIdx.x;
    int w = t >> 5, lane = t & 31;
    int tile = blockIdx.x;
    const uint8_t* xh = d_hchi[1 - parity][1];
    const uint8_t* xl = d_hclo[1 - parity][1];

    auto prefetch = [&](int s) {
        uint32_t sb = dbase + (s & 3) * 40960;
        const uint8_t* wh = d_whiB + ((size_t)tile * 16 + s) * 16384;
        const uint8_t* wl = d_wloB + ((size_t)tile * 16 + s) * 16384;
#pragma unroll
        for (int q = 0; q < 4; q++) {
            int idx = t + 256 * q;
            cpa16(sb + idx * 16, wh + idx * 16);
        }
#pragma unroll
        for (int q = 0; q < 4; q++) {
            int idx = t + 256 * q;
            cpa16(sb + 16384 + idx * 16, wl + idx * 16);
        }
        cpa16(sb + 32768 + t * 16, xh + s * 4096 + t * 16);
        cpa16(sb + 36864 + t * 16, xl + s * 4096 + t * 16);
        cpcommit();
    };
    prefetch(0); prefetch(1); prefetch(2);

    int mrowA = w * 16 + (lane & 7) + ((lane >> 3) & 1) * 8;
    int khA = (lane >> 4) & 1;
    int nrowB = ((lane >> 4) & 1) * 8 + (lane & 7);
    int khB = (lane >> 3) & 1;

    float acc[4][4];
#pragma unroll
    for (int j = 0; j < 4; j++)
#pragma unroll
        for (int q = 0; q < 4; q++) acc[j][q] = 0.f;

    for (int s = 0; s < 16; s++) {
        cpwait2();
        __syncthreads();
        uint32_t sb = dbase + (s & 3) * 40960;
#pragma unroll
        for (int kc = 0; kc < 4; kc++) {
            uint32_t offA = sw128((uint32_t)(mrowA * 128 + kc * 32 + khA * 16));
            uint32_t offB0 = sw128((uint32_t)(nrowB * 128 + kc * 32 + khB * 16));
            uint32_t offB1 = sw128((uint32_t)((nrowB + 16) * 128 + kc * 32 + khB * 16));
            uint32_t ah[4], al[4];
            uint32_t bh[8], bl[8];
            ldsm4(ah, sb + offA);
            ldsm4(al, sb + 16384 + offA);
            ldsm4(bh,     sb + 32768 + offB0);
            ldsm4(bh + 4, sb + 32768 + offB1);
            ldsm4(bl,     sb + 36864 + offB0);
            ldsm4(bl + 4, sb + 36864 + offB1);
#pragma unroll
            for (int nt = 0; nt < 4; nt++) {
                mma16816(acc[nt], ah, bh[nt * 2], bh[nt * 2 + 1]);
                mma16816(acc[nt], al, bh[nt * 2], bh[nt * 2 + 1]);
                mma16816(acc[nt], ah, bl[nt * 2], bl[nt * 2 + 1]);
            }
        }
        __syncthreads();
        if (s + 3 < 16) prefetch(s + 3); else cpcommit();
    }

    float* sv = (float*)dsm;
    __syncthreads();
    int r0 = w * 16 + (lane >> 2);
    int c0 = 2 * (lane & 3);
#pragma unroll
    for (int nt = 0; nt < 4; nt++) {
        int c = nt * 8 + c0;
        sv[r0 * 33 + c]           = acc[nt][0];
        sv[r0 * 33 + c + 1]       = acc[nt][1];
        sv[(r0 + 8) * 33 + c]     = acc[nt][2];
        sv[(r0 + 8) * 33 + c + 1] = acc[nt][3];
    }
    __syncthreads();

    int row = t >> 1;
    int chalf = (t & 1) * 16;
    int gm = tile * 128 + row;
    int valid = gm < VV;
    float bb = valid ? bias[gm] : 0.f;
    size_t obase = (size_t)s_step * BB * VV + gm;
#pragma unroll
    for (int cc = 0; cc < 16; cc++) {
        int c = chalf + cc;
        float v = sv[row * 33 + c] + bb;
        if (valid) outp[obase + (size_t)c * VV] = v;
        sv[row * 33 + c] = valid ? v : -3.402823466e38f;
    }
    __syncthreads();
    if (t < 32) {
        float best = -3.402823466e38f; int bi = 0;
        for (int tt = 0; tt < 128; tt++) {
            float x = sv[tt * 33 + t];
            if (x > best) { best = x; bi = tt; }
        }
        d_pmax[tile * 32 + t] = best;
        d_pidx[tile * 32 + t] = tile * 128 + bi;
    }

    // ---- last block performs select (argmax) + len update + next-step embed ----
    __threadfence();
    __syncthreads();
    __shared__ int lastf;
    if (t == 0) lastf = (atomicAdd(&d_cntp, 1) == NT - 1) ? 1 : 0;
    __syncthreads();
    if (!lastf) return;
    if (t == 0) d_cntp = 0;
    __threadfence();

    __shared__ float rsv[32][8];
    __shared__ int   rsi[32][8];
    {
        int b = t >> 3, q = t & 7;
        float best = -3.402823466e38f; int bi = 0x7fffffff;
        for (int p = q; p < NT; p += 8) {
            float v = d_pmax[p * 32 + b]; int id = d_pidx[p * 32 + b];
            if (v > best || (v == best && id < bi)) { best = v; bi = id; }
        }
        rsv[b][q] = best; rsi[b][q] = bi;
        __syncthreads();
        if (q == 0) {
#pragma unroll
            for (int p = 1; p < 8; p++) {
                float v = rsv[b][p]; int id = rsi[b][p];
                if (v > best || (v == best && id < bi)) { best = v; bi = id; }
            }
            d_tok[b] = bi;
            int r2 = d_run[b] && (bi != 32000);
            d_run[b] = r2;
            if (r2) d_len[b] = s_step + 1;
            if (has_len) outp[(size_t)NSTEP * BB * VV + b] = (float)d_len[b];
        }
    }
    __syncthreads();
    for (int i = t; i < EE * 32; i += 256) {
        int k = i >> 5, b = i & 31;
        float v = emb[(size_t)d_tok[b] * EE + k];
        uint32_t off = (k >> 6) * 4096 + sw128((uint32_t)((b << 7) + ((k & 63) << 1)));
        __nv_bfloat16 hi = __float2bfloat16(v);
        *(__nv_bfloat16*)(&d_xehi[off]) = hi;
        *(__nv_bfloat16*)(&d_xelo[off]) = __float2bfloat16(v - __bfloat162float(hi));
    }
}

// ---------------- launch ----------------
extern "C" void kernel_launch(void* const* d_in, const int* in_sizes, int n_in,
                              void* d_out, int out_size) {
    const float* h0   = (const float*)d_in[2];
    const float* c0   = (const float*)d_in[3];
    const float* emb  = (const float*)d_in[4];
    const float* wih0 = (const float*)d_in[5];
    const float* whh0 = (const float*)d_in[6];
    const float* bih0 = (const float*)d_in[7];
    const float* bhh0 = (const float*)d_in[8];
    const float* wih1 = (const float*)d_in[9];
    const float* whh1 = (const float*)d_in[10];
    const float* bih1 = (const float*)d_in[11];
    const float* bhh1 = (const float*)d_in[12];
    const float* wout = (const float*)d_in[13];
    const float* bout = (const float*)d_in[14];
    float* outp = (float*)d_out;
    int has_len = out_size > NSTEP * BB * VV;

    cudaFuncSetAttribute(k_gmm, cudaFuncAttributeMaxDynamicSharedMemorySize, 163840);
    cudaFuncSetAttribute(k_projMM, cudaFuncAttributeMaxDynamicSharedMemorySize, 163840);

    k_prep<<<256, 256>>>(h0, c0);
    k_prepw<<<dim3(16, NT), 256>>>(wout);
    k_prepg<<<dim3(32, 32, 2), 256>>>(wih0, whh0, wih1, whh1);
    k_embed0<<<BB, 512>>>(emb);

    for (int s = 0; s < NSTEP; s++) {
        int p = s & 1;
        k_gmm<<<dim3(32, KSPL), 256, 163840>>>(0, p, bih0, bhh0);
        k_gmm<<<dim3(32, KSPL), 256, 163840>>>(1, p, bih1, bhh1);
        k_projMM<<<NT, 256, 163840>>>(bout, outp, s, p, emb, has_len);
    }
}

// round 16
// speedup vs baseline: 1.8496x; 1.8496x over previous
#include <cuda_runtime.h>
#include <cuda_bf16.h>
#include <math.h>
#include <stdint.h>

#define BB 32
#define HH 1024
#define EE 512
#define VV 32001
#define NSTEP 32
#define NT 251            // projection tiles of 128 vocab rows
#define KSPL 4            // k-split for gate GEMMs

// ---------------- device state ----------------
__device__ __align__(16) uint8_t d_whiB[NT * 16 * 16384];  // w_out bf16 hi, blocked+swizzled
__device__ __align__(16) uint8_t d_wloB[NT * 16 * 16384];  // w_out bf16 lo
__device__ __align__(16) uint8_t d_g0hi[32 * 24 * 16384];  // layer0 gate w bf16 hi
__device__ __align__(16) uint8_t d_g0lo[32 * 24 * 16384];
__device__ __align__(16) uint8_t d_g1hi[32 * 32 * 16384];  // layer1 gate w bf16 hi
__device__ __align__(16) uint8_t d_g1lo[32 * 32 * 16384];
__device__ __align__(16) uint8_t d_hchi[2][2][16 * 4096];  // h bf16 hi [parity][layer]
__device__ __align__(16) uint8_t d_hclo[2][2][16 * 4096];
__device__ __align__(16) uint8_t d_xehi[8 * 4096];         // embedded x bf16 hi
__device__ __align__(16) uint8_t d_xelo[8 * 4096];
__device__ float d_cst[2 * HH * BB];     // cell state [layer][j][b]
__device__ float d_gp[KSPL * 4096 * BB]; // gate GEMM partials [split][col][b]
__device__ float d_pmax[NT * BB];
__device__ int   d_pidx[NT * BB];
__device__ int   d_tok[BB];
__device__ int   d_run[BB];
__device__ int   d_len[BB];

__device__ __forceinline__ void cpa16(uint32_t d, const void* s) {
    asm volatile("cp.async.cg.shared.global [%0], [%1], 16;" :: "r"(d), "l"(s));
}
__device__ __forceinline__ void cpcommit() { asm volatile("cp.async.commit_group;"); }
__device__ __forceinline__ void cpwait2() { asm volatile("cp.async.wait_group 2;"); }
__device__ __forceinline__ uint32_t sw128(uint32_t off) { return off ^ ((off >> 3) & 0x70); }

__device__ __forceinline__ void ldsm4(uint32_t* r, uint32_t a) {
    asm volatile("ldmatrix.sync.aligned.m8n8.x4.shared.b16 {%0,%1,%2,%3},[%4];"
                 : "=r"(r[0]), "=r"(r[1]), "=r"(r[2]), "=r"(r[3]) : "r"(a));
}
__device__ __forceinline__ void mma16816(float* c, const uint32_t* a, uint32_t b0, uint32_t b1) {
    asm volatile(
        "mma.sync.aligned.m16n8k16.row.col.f32.bf16.bf16.f32 "
        "{%0,%1,%2,%3},{%4,%5,%6,%7},{%8,%9},{%0,%1,%2,%3};"
        : "+f"(c[0]), "+f"(c[1]), "+f"(c[2]), "+f"(c[3])
        : "r"(a[0]), "r"(a[1]), "r"(a[2]), "r"(a[3]), "r"(b0), "r"(b1));
}
__device__ __forceinline__ void export_h(uint8_t* dhi, uint8_t* dlo, int unit, int b, float v) {
    uint32_t off = (unit >> 6) * 4096 + sw128((uint32_t)((b << 7) + ((unit & 63) << 1)));
    __nv_bfloat16 hi = __float2bfloat16(v);
    *(__nv_bfloat16*)(dhi + off) = hi;
    *(__nv_bfloat16*)(dlo + off) = __float2bfloat16(v - __bfloat162float(hi));
}

// ---------------- prep A: state init + initial h bf16 export ----------------
__global__ void __launch_bounds__(256) k_prep(const float* __restrict__ h0,
                                              const float* __restrict__ c0) {
    int i = blockIdx.x * 256 + threadIdx.x;   // < 65536
    int l = i >> 15; int r = i & 32767; int b = r >> 10; int j = r & 1023;
    float hv = h0[i];
    d_cst[(l * 1024 + j) * 32 + b] = c0[i];
    export_h(d_hchi[0][l], d_hclo[0][l], j, b, hv);
    if (i < 32) { d_tok[i] = 32000; d_run[i] = 1; d_len[i] = 0; }
}

// ---------------- prep B: w_out -> bf16 hi/lo, blocked + SW128-swizzled ----------------
__global__ void __launch_bounds__(256) k_prepw(const float* __restrict__ wout) {
    __shared__ __align__(16) uint8_t hbuf[16384];
    __shared__ __align__(16) uint8_t lbuf[16384];
    int chunk = blockIdx.x, tile = blockIdx.y, t = threadIdx.x;
#pragma unroll 4
    for (int i = 0; i < 32; i++) {
        int lin = i * 256 + t;            // 0..8191
        int m = lin >> 6, k = lin & 63;
        int gm = tile * 128 + m;
        float v = (gm < VV) ? wout[(size_t)gm * 1024 + chunk * 64 + k] : 0.f;
        __nv_bfloat16 hi = __float2bfloat16(v);
        __nv_bfloat16 lo = __float2bfloat16(v - __bfloat162float(hi));
        uint32_t off = sw128((uint32_t)(m * 128 + k * 2));
        *(__nv_bfloat16*)(hbuf + off) = hi;
        *(__nv_bfloat16*)(lbuf + off) = lo;
    }
    __syncthreads();
    size_t base = ((size_t)tile * 16 + chunk) * 16384;
#pragma unroll
    for (int q = 0; q < 4; q++) {
        int idx = t + 256 * q;
        ((float4*)(d_whiB + base))[idx] = ((const float4*)hbuf)[idx];
        ((float4*)(d_wloB + base))[idx] = ((const float4*)lbuf)[idx];
    }
}

// ---------------- prep C: gate weights -> bf16 hi/lo blocked tiles ----------------
__global__ void __launch_bounds__(256) k_prepg(const float* __restrict__ wih0,
                                               const float* __restrict__ whh0,
                                               const float* __restrict__ wih1,
                                               const float* __restrict__ whh1) {
    __shared__ __align__(16) uint8_t hbuf[16384];
    __shared__ __align__(16) uint8_t lbuf[16384];
    int chunk = blockIdx.x, tile = blockIdx.y, layer = blockIdx.z, t = threadIdx.x;
    if (!layer && chunk >= 24) return;
    const float* wa = layer ? wih1 : wih0;
    const float* wb = layer ? whh1 : whh0;
    int Ka = layer ? 1024 : 512;
    int NCH = layer ? 32 : 24;
#pragma unroll 4
    for (int i = 0; i < 32; i++) {
        int lin = i * 256 + t;
        int m = lin >> 6, k = lin & 63;
        int kg = chunk * 64 + k;
        int cp = tile * 128 + m;
        int unit = (cp >> 5) * 8 + ((cp >> 2) & 7);
        int gg = cp & 3;
        int row = gg * 1024 + unit;
        float v = (kg < Ka) ? wa[(size_t)row * Ka + kg] : wb[(size_t)row * 1024 + (kg - Ka)];
        __nv_bfloat16 hi = __float2bfloat16(v);
        __nv_bfloat16 lo = __float2bfloat16(v - __bfloat162float(hi));
        uint32_t off = sw128((uint32_t)(m * 128 + k * 2));
        *(__nv_bfloat16*)(hbuf + off) = hi;
        *(__nv_bfloat16*)(lbuf + off) = lo;
    }
    __syncthreads();
    uint8_t* oh = layer ? d_g1hi : d_g0hi;
    uint8_t* ol = layer ? d_g1lo : d_g0lo;
    size_t base = ((size_t)tile * NCH + chunk) * 16384;
#pragma unroll
    for (int q = 0; q < 4; q++) {
        int idx = t + 256 * q;
        ((float4*)(oh + base))[idx] = ((const float4*)hbuf)[idx];
        ((float4*)(ol + base))[idx] = ((const float4*)lbuf)[idx];
    }
}

// ---------------- fused select (parallel argmax) + embedding gather ----------------
__global__ void __launch_bounds__(512) k_selembed(const float* __restrict__ emb,
                                                  float* __restrict__ outp,
                                                  int has_len, int s) {
    __shared__ float sv[4];
    __shared__ int   si[4];
    __shared__ int   stok;
    int b = blockIdx.x;
    int t = threadIdx.x;

    if (s > 0) {
        if (t < 128) {
            float best = -3.402823466e38f; int bi = 0x7fffffff;
            if (t < NT) { best = d_pmax[t * BB + b]; bi = d_pidx[t * BB + b]; }
            int p2 = t + 128;
            if (p2 < NT) {
                float v = d_pmax[p2 * BB + b]; int id = d_pidx[p2 * BB + b];
                if (v > best || (v == best && id < bi)) { best = v; bi = id; }
            }
            // warp tree reduce (4 warps of the first 128 threads)
#pragma unroll
            for (int off = 16; off >= 1; off >>= 1) {
                float ov = __shfl_down_sync(0xFFFFFFFF, best, off);
                int   oi = __shfl_down_sync(0xFFFFFFFF, bi, off);
                if (ov > best || (ov == best && oi < bi)) { best = ov; bi = oi; }
            }
            if ((t & 31) == 0) { sv[t >> 5] = best; si[t >> 5] = bi; }
        }
        __syncthreads();
        if (t == 0) {
            float best = sv[0]; int bi = si[0];
#pragma unroll
            for (int p = 1; p < 4; p++) {
                float v = sv[p]; int id = si[p];
                if (v > best || (v == best && id < bi)) { best = v; bi = id; }
            }
            d_tok[b] = bi;
            stok = bi;
            int r2 = d_run[b] && (bi != 32000);
            d_run[b] = r2;
            if (r2) d_len[b] = s;
            if (has_len) outp[(size_t)NSTEP * BB * VV + b] = (float)d_len[b];
        }
        __syncthreads();
    } else {
        if (t == 0) stok = d_tok[b];
        __syncthreads();
    }
    int tok = stok;
    float v = emb[(size_t)tok * EE + t];
    uint32_t off = (t >> 6) * 4096 + sw128((uint32_t)((b << 7) + ((t & 63) << 1)));
    __nv_bfloat16 hi = __float2bfloat16(v);
    *(__nv_bfloat16*)(&d_xehi[off]) = hi;
    *(__nv_bfloat16*)(&d_xelo[off]) = __float2bfloat16(v - __bfloat162float(hi));
}

// ---------------- gate GEMM via mma.sync: partials [128 gate-cols x 32 batch] ----------------
// grid (32 tiles, KSPL splits), 256 threads; dyn smem 163840 = 4 slots x 40KB
__global__ void __launch_bounds__(256) k_gmm(int layer, int parity) {
    extern __shared__ __align__(16) uint8_t dsm[];
    uint32_t dbase = (uint32_t)__cvta_generic_to_shared(dsm);
    int t = threadIdx.x;
    int w = t >> 5, lane = t & 31;
    int tile = blockIdx.x, split = blockIdx.y;
    const uint8_t* whi = layer ? d_g1hi : d_g0hi;
    const uint8_t* wlo = layer ? d_g1lo : d_g0lo;
    int NCH = layer ? 32 : 24;
    int Q = NCH >> 2;                 // 8 or 6 chunks per split

    auto xhi = [&](int c) -> const uint8_t* {
        if (layer) return (c < 16) ? &d_hchi[1 - parity][0][c * 4096]
                                   : &d_hchi[parity][1][(c - 16) * 4096];
        return (c < 8) ? &d_xehi[c * 4096] : &d_hchi[parity][0][(c - 8) * 4096];
    };
    auto xlo = [&](int c) -> const uint8_t* {
        if (layer) return (c < 16) ? &d_hclo[1 - parity][0][c * 4096]
                                   : &d_hclo[parity][1][(c - 16) * 4096];
        return (c < 8) ? &d_xelo[c * 4096] : &d_hclo[parity][0][(c - 8) * 4096];
    };

    auto prefetch = [&](int s) {
        int ci = split * Q + s;
        uint32_t sb = dbase + (s & 3) * 40960;
        const uint8_t* wh = whi + ((size_t)tile * NCH + ci) * 16384;
        const uint8_t* wl = wlo + ((size_t)tile * NCH + ci) * 16384;
#pragma unroll
        for (int q = 0; q < 4; q++) {
            int idx = t + 256 * q;
            cpa16(sb + idx * 16, wh + idx * 16);
        }
#pragma unroll
        for (int q = 0; q < 4; q++) {
            int idx = t + 256 * q;
            cpa16(sb + 16384 + idx * 16, wl + idx * 16);
        }
        cpa16(sb + 32768 + t * 16, xhi(ci) + t * 16);
        cpa16(sb + 36864 + t * 16, xlo(ci) + t * 16);
        cpcommit();
    };
    prefetch(0); prefetch(1); prefetch(2);

    int mrowA = w * 16 + (lane & 7) + ((lane >> 3) & 1) * 8;
    int khA = (lane >> 4) & 1;
    int nrowB = ((lane >> 4) & 1) * 8 + (lane & 7);
    int khB = (lane >> 3) & 1;

    float acc[4][4];
#pragma unroll
    for (int j = 0; j < 4; j++)
#pragma unroll
        for (int q = 0; q < 4; q++) acc[j][q] = 0.f;

    for (int s = 0; s < Q; s++) {
        cpwait2();
        __syncthreads();
        uint32_t sb = dbase + (s & 3) * 40960;
#pragma unroll
        for (int kc = 0; kc < 4; kc++) {
            uint32_t offA = sw128((uint32_t)(mrowA * 128 + kc * 32 + khA * 16));
            uint32_t offB0 = sw128((uint32_t)(nrowB * 128 + kc * 32 + khB * 16));
            uint32_t offB1 = sw128((uint32_t)((nrowB + 16) * 128 + kc * 32 + khB * 16));
            uint32_t ah[4], al[4];
            uint32_t bh[8], bl[8];
            ldsm4(ah, sb + offA);
            ldsm4(al, sb + 16384 + offA);
            ldsm4(bh,     sb + 32768 + offB0);
            ldsm4(bh + 4, sb + 32768 + offB1);
            ldsm4(bl,     sb + 36864 + offB0);
            ldsm4(bl + 4, sb + 36864 + offB1);
#pragma unroll
            for (int nt = 0; nt < 4; nt++) {
                mma16816(acc[nt], ah, bh[nt * 2], bh[nt * 2 + 1]);
                mma16816(acc[nt], al, bh[nt * 2], bh[nt * 2 + 1]);
                mma16816(acc[nt], ah, bl[nt * 2], bl[nt * 2 + 1]);
            }
        }
        __syncthreads();
        if (s + 3 < Q) prefetch(s + 3); else cpcommit();
    }

    // epilogue: fragments -> smem, then fp32 partial store
    float* sv = (float*)dsm;
    __syncthreads();
    int r0 = w * 16 + (lane >> 2);
    int c0 = 2 * (lane & 3);
#pragma unroll
    for (int nt = 0; nt < 4; nt++) {
        int c = nt * 8 + c0;
        sv[r0 * 33 + c]           = acc[nt][0];
        sv[r0 * 33 + c + 1]       = acc[nt][1];
        sv[(r0 + 8) * 33 + c]     = acc[nt][2];
        sv[(r0 + 8) * 33 + c + 1] = acc[nt][3];
    }
    __syncthreads();

    int row = t >> 1;
    int chalf = (t & 1) * 16;
    size_t base = ((size_t)split * 4096 + tile * 128 + row) * 32 + chalf;
#pragma unroll
    for (int cc = 0; cc < 16; cc++)
        d_gp[base + cc] = sv[row * 33 + chalf + cc];
}

// ---------------- LSTM elementwise update + bf16 hi/lo h-export ----------------
__global__ void k_update2(const float* __restrict__ bih, const float* __restrict__ bhh,
                          int layer, int parity) {
    int g = blockIdx.x * 256 + threadIdx.x;
    int unit = g >> 5, b = g & 31;
    int colb = (unit >> 3) * 32 + (unit & 7) * 4;
    float a[4];
#pragma unroll
    for (int q = 0; q < 4; q++) a[q] = bih[q * 1024 + unit] + bhh[q * 1024 + unit];
#pragma unroll
    for (int ks = 0; ks < KSPL; ks++)
#pragma unroll
        for (int q = 0; q < 4; q++)
            a[q] += d_gp[((size_t)ks * 4096 + colb + q) * BB + b];

    int ci = (layer * HH + unit) * BB + b;
    float c = d_cst[ci];
    float ig = 1.f / (1.f + expf(-a[0]));
    float fg = 1.f / (1.f + expf(-a[1]));
    float gt = tanhf(a[2]);
    float og = 1.f / (1.f + expf(-a[3]));
    float c2 = fg * c + ig * gt;
    d_cst[ci] = c2;
    float hv = og * tanhf(c2);
    export_h(d_hchi[1 - parity][layer], d_hclo[1 - parity][layer], unit, b, hv);
}

// ---------------- tensor-core projection via mma.sync: D[128 vocab x 32 batch] ----------------
// grid NT, 256 threads (8 warps); dyn smem 163840 = 4 slots x 40KB
__global__ void __launch_bounds__(256) k_projMM(const float* __restrict__ bias,
                                                float* __restrict__ outp, int s_step,
                                                int parity) {
    extern __shared__ __align__(16) uint8_t dsm[];
    uint32_t dbase = (uint32_t)__cvta_generic_to_shared(dsm);
    int t = threadIdx.x;
    int w = t >> 5, lane = t & 31;
    int tile = blockIdx.x;
    const uint8_t* xh = d_hchi[1 - parity][1];
    const uint8_t* xl = d_hclo[1 - parity][1];

    auto prefetch = [&](int s) {
        uint32_t sb = dbase + (s & 3) * 40960;
        const uint8_t* wh = d_whiB + ((size_t)tile * 16 + s) * 16384;
        const uint8_t* wl = d_wloB + ((size_t)tile * 16 + s) * 16384;
#pragma unroll
        for (int q = 0; q < 4; q++) {
            int idx = t + 256 * q;
            cpa16(sb + idx * 16, wh + idx * 16);
        }
#pragma unroll
        for (int q = 0; q < 4; q++) {
            int idx = t + 256 * q;
            cpa16(sb + 16384 + idx * 16, wl + idx * 16);
        }
        cpa16(sb + 32768 + t * 16, xh + s * 4096 + t * 16);
        cpa16(sb + 36864 + t * 16, xl + s * 4096 + t * 16);
        cpcommit();
    };
    prefetch(0); prefetch(1); prefetch(2);

    int mrowA = w * 16 + (lane & 7) + ((lane >> 3) & 1) * 8;
    int khA = (lane >> 4) & 1;
    int nrowB = ((lane >> 4) & 1) * 8 + (lane & 7);
    int khB = (lane >> 3) & 1;

    float acc[4][4];
#pragma unroll
    for (int j = 0; j < 4; j++)
#pragma unroll
        for (int q = 0; q < 4; q++) acc[j][q] = 0.f;

    for (int s = 0; s < 16; s++) {
        cpwait2();
        __syncthreads();
        uint32_t sb = dbase + (s & 3) * 40960;
#pragma unroll
        for (int kc = 0; kc < 4; kc++) {
            uint32_t offA = sw128((uint32_t)(mrowA * 128 + kc * 32 + khA * 16));
            uint32_t offB0 = sw128((uint32_t)(nrowB * 128 + kc * 32 + khB * 16));
            uint32_t offB1 = sw128((uint32_t)((nrowB + 16) * 128 + kc * 32 + khB * 16));
            uint32_t ah[4], al[4];
            uint32_t bh[8], bl[8];
            ldsm4(ah, sb + offA);
            ldsm4(al, sb + 16384 + offA);
            ldsm4(bh,     sb + 32768 + offB0);
            ldsm4(bh + 4, sb + 32768 + offB1);
            ldsm4(bl,     sb + 36864 + offB0);
            ldsm4(bl + 4, sb + 36864 + offB1);
#pragma unroll
            for (int nt = 0; nt < 4; nt++) {
                mma16816(acc[nt], ah, bh[nt * 2], bh[nt * 2 + 1]);
                mma16816(acc[nt], al, bh[nt * 2], bh[nt * 2 + 1]);
                mma16816(acc[nt], ah, bl[nt * 2], bl[nt * 2 + 1]);
            }
        }
        __syncthreads();
        if (s + 3 < 16) prefetch(s + 3); else cpcommit();
    }

    float* sv = (float*)dsm;
    __syncthreads();
    int r0 = w * 16 + (lane >> 2);
    int c0 = 2 * (lane & 3);
#pragma unroll
    for (int nt = 0; nt < 4; nt++) {
        int c = nt * 8 + c0;
        sv[r0 * 33 + c]           = acc[nt][0];
        sv[r0 * 33 + c + 1]       = acc[nt][1];
        sv[(r0 + 8) * 33 + c]     = acc[nt][2];
        sv[(r0 + 8) * 33 + c + 1] = acc[nt][3];
    }
    __syncthreads();

    int row = t >> 1;
    int chalf = (t & 1) * 16;
    int gm = tile * 128 + row;
    int valid = gm < VV;
    float bb = valid ? bias[gm] : 0.f;
    size_t obase = (size_t)s_step * BB * VV + gm;
#pragma unroll
    for (int cc = 0; cc < 16; cc++) {
        int c = chalf + cc;
        float v = sv[row * 33 + c] + bb;
        if (valid) outp[obase + (size_t)c * VV] = v;
        sv[row * 33 + c] = valid ? v : -3.402823466e38f;
    }
    __syncthreads();
    if (t < 32) {
        float best = -3.402823466e38f; int bi = 0;
        for (int tt = 0; tt < 128; tt++) {
            float x = sv[tt * 33 + t];
            if (x > best) { best = x; bi = tt; }
        }
        d_pmax[tile * 32 + t] = best;
        d_pidx[tile * 32 + t] = tile * 128 + bi;
    }
}

// ---------------- launch ----------------
extern "C" void kernel_launch(void* const* d_in, const int* in_sizes, int n_in,
                              void* d_out, int out_size) {
    const float* h0   = (const float*)d_in[2];
    const float* c0   = (const float*)d_in[3];
    const float* emb  = (const float*)d_in[4];
    const float* wih0 = (const float*)d_in[5];
    const float* whh0 = (const float*)d_in[6];
    const float* bih0 = (const float*)d_in[7];
    const float* bhh0 = (const float*)d_in[8];
    const float* wih1 = (const float*)d_in[9];
    const float* whh1 = (const float*)d_in[10];
    const float* bih1 = (const float*)d_in[11];
    const float* bhh1 = (const float*)d_in[12];
    const float* wout = (const float*)d_in[13];
    const float* bout = (const float*)d_in[14];
    float* outp = (float*)d_out;
    int has_len = out_size > NSTEP * BB * VV;

    cudaFuncSetAttribute(k_gmm, cudaFuncAttributeMaxDynamicSharedMemorySize, 163840);
    cudaFuncSetAttribute(k_projMM, cudaFuncAttributeMaxDynamicSharedMemorySize, 163840);

    k_prep<<<256, 256>>>(h0, c0);
    k_prepw<<<dim3(16, NT), 256>>>(wout);
    k_prepg<<<dim3(32, 32, 2), 256>>>(wih0, whh0, wih1, whh1);

    for (int s = 0; s < NSTEP; s++) {
        int p = s & 1;
        k_selembed<<<BB, 512>>>(emb, outp, has_len, s);
        k_gmm<<<dim3(32, KSPL), 256, 163840>>>(0, p);
        k_update2<<<128, 256>>>(bih0, bhh0, 0, p);
        k_gmm<<<dim3(32, KSPL), 256, 163840>>>(1, p);
        k_update2<<<128, 256>>>(bih1, bhh1, 1, p);
        k_projMM<<<NT, 256, 163840>>>(bout, outp, s, p);
    }
    k_selembed<<<BB, 512>>>(emb, outp, has_len, NSTEP);
}

// round 17
// speedup vs baseline: 1.9809x; 1.0710x over previous
#include <cuda_runtime.h>
#include <cuda_bf16.h>
#include <math.h>
#include <stdint.h>

#define BB 32
#define HH 1024
#define EE 512
#define VV 32001
#define NSTEP 32
#define NTW 252           // 128-row weight tiles (252*128 = 32256, pad zeros)
#define NPT 126           // projection blocks (256 vocab rows each)
#define KSPL 4            // k-split for gate GEMMs

// ---------------- device state ----------------
__device__ __align__(16) uint8_t d_whiB[NTW * 16 * 16384]; // w_out bf16 hi, blocked+swizzled
__device__ __align__(16) uint8_t d_wloB[NTW * 16 * 16384]; // w_out bf16 lo
__device__ __align__(16) uint8_t d_g0hi[32 * 24 * 16384];  // layer0 gate w bf16 hi
__device__ __align__(16) uint8_t d_g0lo[32 * 24 * 16384];
__device__ __align__(16) uint8_t d_g1hi[32 * 32 * 16384];  // layer1 gate w bf16 hi
__device__ __align__(16) uint8_t d_g1lo[32 * 32 * 16384];
__device__ __align__(16) uint8_t d_hchi[2][2][16 * 4096];  // h bf16 hi [parity][layer]
__device__ __align__(16) uint8_t d_hclo[2][2][16 * 4096];
__device__ __align__(16) uint8_t d_xehi[8 * 4096];         // embedded x bf16 hi
__device__ __align__(16) uint8_t d_xelo[8 * 4096];
__device__ float d_cst[2 * HH * BB];     // cell state [layer][j][b]
__device__ float d_gp[KSPL * 4096 * BB]; // gate GEMM partials [split][col][b]
__device__ float d_pmax[NPT * BB];
__device__ int   d_pidx[NPT * BB];
__device__ int   d_tok[BB];
__device__ int   d_run[BB];
__device__ int   d_len[BB];

__device__ __forceinline__ void cpa16(uint32_t d, const void* s) {
    asm volatile("cp.async.cg.shared.global [%0], [%1], 16;" :: "r"(d), "l"(s));
}
__device__ __forceinline__ void cpcommit() { asm volatile("cp.async.commit_group;"); }
__device__ __forceinline__ void cpwait2() { asm volatile("cp.async.wait_group 2;"); }
__device__ __forceinline__ uint32_t sw128(uint32_t off) { return off ^ ((off >> 3) & 0x70); }

__device__ __forceinline__ void ldsm4(uint32_t* r, uint32_t a) {
    asm volatile("ldmatrix.sync.aligned.m8n8.x4.shared.b16 {%0,%1,%2,%3},[%4];"
                 : "=r"(r[0]), "=r"(r[1]), "=r"(r[2]), "=r"(r[3]) : "r"(a));
}
__device__ __forceinline__ void mma16816(float* c, const uint32_t* a, uint32_t b0, uint32_t b1) {
    asm volatile(
        "mma.sync.aligned.m16n8k16.row.col.f32.bf16.bf16.f32 "
        "{%0,%1,%2,%3},{%4,%5,%6,%7},{%8,%9},{%0,%1,%2,%3};"
        : "+f"(c[0]), "+f"(c[1]), "+f"(c[2]), "+f"(c[3])
        : "r"(a[0]), "r"(a[1]), "r"(a[2]), "r"(a[3]), "r"(b0), "r"(b1));
}
__device__ __forceinline__ void export_h(uint8_t* dhi, uint8_t* dlo, int unit, int b, float v) {
    uint32_t off = (unit >> 6) * 4096 + sw128((uint32_t)((b << 7) + ((unit & 63) << 1)));
    __nv_bfloat16 hi = __float2bfloat16(v);
    *(__nv_bfloat16*)(dhi + off) = hi;
    *(__nv_bfloat16*)(dlo + off) = __float2bfloat16(v - __bfloat162float(hi));
}

// ---------------- prep A: state init + initial h bf16 export ----------------
__global__ void __launch_bounds__(256) k_prep(const float* __restrict__ h0,
                                              const float* __restrict__ c0) {
    int i = blockIdx.x * 256 + threadIdx.x;   // < 65536
    int l = i >> 15; int r = i & 32767; int b = r >> 10; int j = r & 1023;
    float hv = h0[i];
    d_cst[(l * 1024 + j) * 32 + b] = c0[i];
    export_h(d_hchi[0][l], d_hclo[0][l], j, b, hv);
    if (i < 32) { d_tok[i] = 32000; d_run[i] = 1; d_len[i] = 0; }
}

// ---------------- prep B: w_out -> bf16 hi/lo, blocked + SW128-swizzled ----------------
__global__ void __launch_bounds__(256) k_prepw(const float* __restrict__ wout) {
    __shared__ __align__(16) uint8_t hbuf[16384];
    __shared__ __align__(16) uint8_t lbuf[16384];
    int chunk = blockIdx.x, tile = blockIdx.y, t = threadIdx.x;
#pragma unroll 4
    for (int i = 0; i < 32; i++) {
        int lin = i * 256 + t;            // 0..8191
        int m = lin >> 6, k = lin & 63;
        int gm = tile * 128 + m;
        float v = (gm < VV) ? wout[(size_t)gm * 1024 + chunk * 64 + k] : 0.f;
        __nv_bfloat16 hi = __float2bfloat16(v);
        __nv_bfloat16 lo = __float2bfloat16(v - __bfloat162float(hi));
        uint32_t off = sw128((uint32_t)(m * 128 + k * 2));
        *(__nv_bfloat16*)(hbuf + off) = hi;
        *(__nv_bfloat16*)(lbuf + off) = lo;
    }
    __syncthreads();
    size_t base = ((size_t)tile * 16 + chunk) * 16384;
#pragma unroll
    for (int q = 0; q < 4; q++) {
        int idx = t + 256 * q;
        ((float4*)(d_whiB + base))[idx] = ((const float4*)hbuf)[idx];
        ((float4*)(d_wloB + base))[idx] = ((const float4*)lbuf)[idx];
    }
}

// ---------------- prep C: gate weights -> bf16 hi/lo blocked tiles ----------------
__global__ void __launch_bounds__(256) k_prepg(const float* __restrict__ wih0,
                                               const float* __restrict__ whh0,
                                               const float* __restrict__ wih1,
                                               const float* __restrict__ whh1) {
    __shared__ __align__(16) uint8_t hbuf[16384];
    __shared__ __align__(16) uint8_t lbuf[16384];
    int chunk = blockIdx.x, tile = blockIdx.y, layer = blockIdx.z, t = threadIdx.x;
    if (!layer && chunk >= 24) return;
    const float* wa = layer ? wih1 : wih0;
    const float* wb = layer ? whh1 : whh0;
    int Ka = layer ? 1024 : 512;
    int NCH = layer ? 32 : 24;
#pragma unroll 4
    for (int i = 0; i < 32; i++) {
        int lin = i * 256 + t;
        int m = lin >> 6, k = lin & 63;
        int kg = chunk * 64 + k;
        int cp = tile * 128 + m;
        int unit = (cp >> 5) * 8 + ((cp >> 2) & 7);
        int gg = cp & 3;
        int row = gg * 1024 + unit;
        float v = (kg < Ka) ? wa[(size_t)row * Ka + kg] : wb[(size_t)row * 1024 + (kg - Ka)];
        __nv_bfloat16 hi = __float2bfloat16(v);
        __nv_bfloat16 lo = __float2bfloat16(v - __bfloat162float(hi));
        uint32_t off = sw128((uint32_t)(m * 128 + k * 2));
        *(__nv_bfloat16*)(hbuf + off) = hi;
        *(__nv_bfloat16*)(lbuf + off) = lo;
    }
    __syncthreads();
    uint8_t* oh = layer ? d_g1hi : d_g0hi;
    uint8_t* ol = layer ? d_g1lo : d_g0lo;
    size_t base = ((size_t)tile * NCH + chunk) * 16384;
#pragma unroll
    for (int q = 0; q < 4; q++) {
        int idx = t + 256 * q;
        ((float4*)(oh + base))[idx] = ((const float4*)hbuf)[idx];
        ((float4*)(ol + base))[idx] = ((const float4*)lbuf)[idx];
    }
}

// ---------------- fused select (parallel argmax) + embedding gather ----------------
__global__ void __launch_bounds__(512) k_selembed(const float* __restrict__ emb,
                                                  float* __restrict__ outp,
                                                  int has_len, int s) {
    __shared__ float sv[4];
    __shared__ int   si[4];
    __shared__ int   stok;
    int b = blockIdx.x;
    int t = threadIdx.x;

    if (s > 0) {
        if (t < 128) {
            float best = -3.402823466e38f; int bi = 0x7fffffff;
            if (t < NPT) { best = d_pmax[t * BB + b]; bi = d_pidx[t * BB + b]; }
#pragma unroll
            for (int off = 16; off >= 1; off >>= 1) {
                float ov = __shfl_down_sync(0xFFFFFFFF, best, off);
                int   oi = __shfl_down_sync(0xFFFFFFFF, bi, off);
                if (ov > best || (ov == best && oi < bi)) { best = ov; bi = oi; }
            }
            if ((t & 31) == 0) { sv[t >> 5] = best; si[t >> 5] = bi; }
        }
        __syncthreads();
        if (t == 0) {
            float best = sv[0]; int bi = si[0];
#pragma unroll
            for (int p = 1; p < 4; p++) {
                float v = sv[p]; int id = si[p];
                if (v > best || (v == best && id < bi)) { best = v; bi = id; }
            }
            d_tok[b] = bi;
            stok = bi;
            int r2 = d_run[b] && (bi != 32000);
            d_run[b] = r2;
            if (r2) d_len[b] = s;
            if (has_len) outp[(size_t)NSTEP * BB * VV + b] = (float)d_len[b];
        }
        __syncthreads();
    } else {
        if (t == 0) stok = d_tok[b];
        __syncthreads();
    }
    int tok = stok;
    float v = emb[(size_t)tok * EE + t];
    uint32_t off = (t >> 6) * 4096 + sw128((uint32_t)((b << 7) + ((t & 63) << 1)));
    __nv_bfloat16 hi = __float2bfloat16(v);
    *(__nv_bfloat16*)(&d_xehi[off]) = hi;
    *(__nv_bfloat16*)(&d_xelo[off]) = __float2bfloat16(v - __bfloat162float(hi));
}

// ---------------- gate GEMM via mma.sync: partials [128 gate-cols x 32 batch] ----------------
// grid (32 tiles, KSPL splits), 256 threads; dyn smem 163840 = 4 slots x 40KB
__global__ void __launch_bounds__(256) k_gmm(int layer, int parity) {
    extern __shared__ __align__(16) uint8_t dsm[];
    uint32_t dbase = (uint32_t)__cvta_generic_to_shared(dsm);
    int t = threadIdx.x;
    int w = t >> 5, lane = t & 31;
    int tile = blockIdx.x, split = blockIdx.y;
    const uint8_t* whi = layer ? d_g1hi : d_g0hi;
    const uint8_t* wlo = layer ? d_g1lo : d_g0lo;
    int NCH = layer ? 32 : 24;
    int Q = NCH >> 2;                 // 8 or 6 chunks per split

    auto xhi = [&](int c) -> const uint8_t* {
        if (layer) return (c < 16) ? &d_hchi[1 - parity][0][c * 4096]
                                   : &d_hchi[parity][1][(c - 16) * 4096];
        return (c < 8) ? &d_xehi[c * 4096] : &d_hchi[parity][0][(c - 8) * 4096];
    };
    auto xlo = [&](int c) -> const uint8_t* {
        if (layer) return (c < 16) ? &d_hclo[1 - parity][0][c * 4096]
                                   : &d_hclo[parity][1][(c - 16) * 4096];
        return (c < 8) ? &d_xelo[c * 4096] : &d_hclo[parity][0][(c - 8) * 4096];
    };

    auto prefetch = [&](int s) {
        int ci = split * Q + s;
        uint32_t sb = dbase + (s & 3) * 40960;
        const uint8_t* wh = whi + ((size_t)tile * NCH + ci) * 16384;
        const uint8_t* wl = wlo + ((size_t)tile * NCH + ci) * 16384;
#pragma unroll
        for (int q = 0; q < 4; q++) {
            int idx = t + 256 * q;
            cpa16(sb + idx * 16, wh + idx * 16);
        }
#pragma unroll
        for (int q = 0; q < 4; q++) {
            int idx = t + 256 * q;
            cpa16(sb + 16384 + idx * 16, wl + idx * 16);
        }
        cpa16(sb + 32768 + t * 16, xhi(ci) + t * 16);
        cpa16(sb + 36864 + t * 16, xlo(ci) + t * 16);
        cpcommit();
    };
    prefetch(0); prefetch(1); prefetch(2);

    int mrowA = w * 16 + (lane & 7) + ((lane >> 3) & 1) * 8;
    int khA = (lane >> 4) & 1;
    int nrowB = ((lane >> 4) & 1) * 8 + (lane & 7);
    int khB = (lane >> 3) & 1;

    float acc[4][4];
#pragma unroll
    for (int j = 0; j < 4; j++)
#pragma unroll
        for (int q = 0; q < 4; q++) acc[j][q] = 0.f;

    for (int s = 0; s < Q; s++) {
        cpwait2();
        __syncthreads();
        uint32_t sb = dbase + (s & 3) * 40960;
#pragma unroll
        for (int kc = 0; kc < 4; kc++) {
            uint32_t offA = sw128((uint32_t)(mrowA * 128 + kc * 32 + khA * 16));
            uint32_t offB0 = sw128((uint32_t)(nrowB * 128 + kc * 32 + khB * 16));
            uint32_t offB1 = sw128((uint32_t)((nrowB + 16) * 128 + kc * 32 + khB * 16));
            uint32_t ah[4], al[4];
            uint32_t bh[8], bl[8];
            ldsm4(ah, sb + offA);
            ldsm4(al, sb + 16384 + offA);
            ldsm4(bh,     sb + 32768 + offB0);
            ldsm4(bh + 4, sb + 32768 + offB1);
            ldsm4(bl,     sb + 36864 + offB0);
            ldsm4(bl + 4, sb + 36864 + offB1);
#pragma unroll
            for (int nt = 0; nt < 4; nt++) {
                mma16816(acc[nt], ah, bh[nt * 2], bh[nt * 2 + 1]);
                mma16816(acc[nt], al, bh[nt * 2], bh[nt * 2 + 1]);
                mma16816(acc[nt], ah, bl[nt * 2], bl[nt * 2 + 1]);
            }
        }
        __syncthreads();
        if (s + 3 < Q) prefetch(s + 3); else cpcommit();
    }

    // epilogue: fragments -> smem, then fp32 partial store
    float* sv = (float*)dsm;
    __syncthreads();
    int r0 = w * 16 + (lane >> 2);
    int c0 = 2 * (lane & 3);
#pragma unroll
    for (int nt = 0; nt < 4; nt++) {
        int c = nt * 8 + c0;
        sv[r0 * 33 + c]           = acc[nt][0];
        sv[r0 * 33 + c + 1]       = acc[nt][1];
        sv[(r0 + 8) * 33 + c]     = acc[nt][2];
        sv[(r0 + 8) * 33 + c + 1] = acc[nt][3];
    }
    __syncthreads();

    int row = t >> 1;
    int chalf = (t & 1) * 16;
    size_t base = ((size_t)split * 4096 + tile * 128 + row) * 32 + chalf;
#pragma unroll
    for (int cc = 0; cc < 16; cc++)
        d_gp[base + cc] = sv[row * 33 + chalf + cc];
}

// ---------------- LSTM elementwise update + bf16 hi/lo h-export ----------------
__global__ void k_update2(const float* __restrict__ bih, const float* __restrict__ bhh,
                          int layer, int parity) {
    int g = blockIdx.x * 256 + threadIdx.x;
    int unit = g >> 5, b = g & 31;
    int colb = (unit >> 3) * 32 + (unit & 7) * 4;
    float a[4];
#pragma unroll
    for (int q = 0; q < 4; q++) a[q] = bih[q * 1024 + unit] + bhh[q * 1024 + unit];
#pragma unroll
    for (int ks = 0; ks < KSPL; ks++)
#pragma unroll
        for (int q = 0; q < 4; q++)
            a[q] += d_gp[((size_t)ks * 4096 + colb + q) * BB + b];

    int ci = (layer * HH + unit) * BB + b;
    float c = d_cst[ci];
    float ig = 1.f / (1.f + expf(-a[0]));
    float fg = 1.f / (1.f + expf(-a[1]));
    float gt = tanhf(a[2]);
    float og = 1.f / (1.f + expf(-a[3]));
    float c2 = fg * c + ig * gt;
    d_cst[ci] = c2;
    float hv = og * tanhf(c2);
    export_h(d_hchi[1 - parity][layer], d_hclo[1 - parity][layer], unit, b, hv);
}

// ---------------- tensor-core projection: D[256 vocab x 32 batch] per block ----------------
// grid NPT, 256 threads (8 warps, 32 vocab rows each); dyn smem 221184 = 3 slots x 73728
__global__ void __launch_bounds__(256) k_projMM(const float* __restrict__ bias,
                                                float* __restrict__ outp, int s_step,
                                                int parity) {
    extern __shared__ __align__(16) uint8_t dsm[];
    uint32_t dbase = (uint32_t)__cvta_generic_to_shared(dsm);
    int t = threadIdx.x;
    int w = t >> 5, lane = t & 31;
    int tile = blockIdx.x;
    const uint8_t* xh = d_hchi[1 - parity][1];
    const uint8_t* xl = d_hclo[1 - parity][1];

    // slot layout (73728 B): [0 whi_t0][16384 whi_t1][32768 wlo_t0][49152 wlo_t1][65536 xhi][69632 xlo]
    auto prefetch = [&](int s) {
        uint32_t sb = dbase + (s % 3) * 73728;
        const uint8_t* wh0 = d_whiB + ((size_t)(2 * tile) * 16 + s) * 16384;
        const uint8_t* wh1 = d_whiB + ((size_t)(2 * tile + 1) * 16 + s) * 16384;
        const uint8_t* wl0 = d_wloB + ((size_t)(2 * tile) * 16 + s) * 16384;
        const uint8_t* wl1 = d_wloB + ((size_t)(2 * tile + 1) * 16 + s) * 16384;
#pragma unroll
        for (int q = 0; q < 4; q++) {
            int idx = t + 256 * q;
            cpa16(sb + idx * 16, wh0 + idx * 16);
            cpa16(sb + 16384 + idx * 16, wh1 + idx * 16);
            cpa16(sb + 32768 + idx * 16, wl0 + idx * 16);
            cpa16(sb + 49152 + idx * 16, wl1 + idx * 16);
        }
        cpa16(sb + 65536 + t * 16, xh + s * 4096 + t * 16);
        cpa16(sb + 69632 + t * 16, xl + s * 4096 + t * 16);
        cpcommit();
    };
    prefetch(0); prefetch(1); prefetch(2);

    // A: warp w owns vocab rows w*32..w*32+31 (two 16-row m-tiles)
    int arow = w * 32 + (lane & 7) + ((lane >> 3) & 1) * 8;   // 0..255 (mt0 row)
    uint32_t abase = (w >= 4) ? 16384u : 0u;
    int ar = arow & 127;                                       // row within 128-tile
    int khA = (lane >> 4) & 1;
    int nrowB = ((lane >> 4) & 1) * 8 + (lane & 7);
    int khB = (lane >> 3) & 1;

    float acc[2][4][4];
#pragma unroll
    for (int i = 0; i < 2; i++)
#pragma unroll
        for (int j = 0; j < 4; j++)
#pragma unroll
            for (int q = 0; q < 4; q++) acc[i][j][q] = 0.f;

    for (int s = 0; s < 16; s++) {
        cpwait2();
        __syncthreads();
        uint32_t sb = dbase + (s % 3) * 73728;
#pragma unroll
        for (int kc = 0; kc < 4; kc++) {
            uint32_t offA0 = abase + sw128((uint32_t)(ar * 128 + kc * 32 + khA * 16));
            uint32_t offA1 = abase + sw128((uint32_t)((ar + 16) * 128 + kc * 32 + khA * 16));
            uint32_t offB0 = sw128((uint32_t)(nrowB * 128 + kc * 32 + khB * 16));
            uint32_t offB1 = sw128((uint32_t)((nrowB + 16) * 128 + kc * 32 + khB * 16));
            uint32_t ah0[4], ah1[4], al0[4], al1[4];
            uint32_t bh[8], bl[8];
            ldsm4(ah0, sb + offA0);
            ldsm4(ah1, sb + offA1);
            ldsm4(al0, sb + 32768 + offA0);
            ldsm4(al1, sb + 32768 + offA1);
            ldsm4(bh,     sb + 65536 + offB0);
            ldsm4(bh + 4, sb + 65536 + offB1);
            ldsm4(bl,     sb + 69632 + offB0);
            ldsm4(bl + 4, sb + 69632 + offB1);
#pragma unroll
            for (int nt = 0; nt < 4; nt++) {
                mma16816(acc[0][nt], ah0, bh[nt * 2], bh[nt * 2 + 1]);
                mma16816(acc[1][nt], ah1, bh[nt * 2], bh[nt * 2 + 1]);
                mma16816(acc[0][nt], al0, bh[nt * 2], bh[nt * 2 + 1]);
                mma16816(acc[1][nt], al1, bh[nt * 2], bh[nt * 2 + 1]);
                mma16816(acc[0][nt], ah0, bl[nt * 2], bl[nt * 2 + 1]);
                mma16816(acc[1][nt], ah1, bl[nt * 2], bl[nt * 2 + 1]);
            }
        }
        __syncthreads();
        if (s + 3 < 16) prefetch(s + 3); else cpcommit();
    }

    // epilogue: fragments -> smem sv[256][33], coalesced store + argmax partials
    float* sv = (float*)dsm;
    __syncthreads();
    int r0 = w * 32 + (lane >> 2);
    int c0 = 2 * (lane & 3);
#pragma unroll
    for (int mt = 0; mt < 2; mt++)
#pragma unroll
        for (int nt = 0; nt < 4; nt++) {
            int r = r0 + mt * 16, c = nt * 8 + c0;
            sv[r * 33 + c]           = acc[mt][nt][0];
            sv[r * 33 + c + 1]       = acc[mt][nt][1];
            sv[(r + 8) * 33 + c]     = acc[mt][nt][2];
            sv[(r + 8) * 33 + c + 1] = acc[mt][nt][3];
        }
    __syncthreads();

    int gm = tile * 256 + t;          // thread t owns vocab row gm, 32 batches
    int valid = gm < VV;
    float bb = valid ? bias[gm] : 0.f;
    size_t obase = (size_t)s_step * BB * VV + gm;
#pragma unroll
    for (int c = 0; c < 32; c++) {
        float v = sv[t * 33 + c] + bb;
        if (valid) outp[obase + (size_t)c * VV] = v;
        sv[t * 33 + c] = valid ? v : -3.402823466e38f;
    }
    __syncthreads();
    if (t < 32) {
        float best = -3.402823466e38f; int bi = 0;
        for (int tt = 0; tt < 256; tt++) {
            float x = sv[tt * 33 + t];
            if (x > best) { best = x; bi = tt; }
        }
        d_pmax[tile * 32 + t] = best;
        d_pidx[tile * 32 + t] = tile * 256 + bi;
    }
}

// ---------------- launch ----------------
extern "C" void kernel_launch(void* const* d_in, const int* in_sizes, int n_in,
                              void* d_out, int out_size) {
    const float* h0   = (const float*)d_in[2];
    const float* c0   = (const float*)d_in[3];
    const float* emb  = (const float*)d_in[4];
    const float* wih0 = (const float*)d_in[5];
    const float* whh0 = (const float*)d_in[6];
    const float* bih0 = (const float*)d_in[7];
    const float* bhh0 = (const float*)d_in[8];
    const float* wih1 = (const float*)d_in[9];
    const float* whh1 = (const float*)d_in[10];
    const float* bih1 = (const float*)d_in[11];
    const float* bhh1 = (const float*)d_in[12];
    const float* wout = (const float*)d_in[13];
    const float* bout = (const float*)d_in[14];
    float* outp = (float*)d_out;
    int has_len = out_size > NSTEP * BB * VV;

    cudaFuncSetAttribute(k_gmm, cudaFuncAttributeMaxDynamicSharedMemorySize, 163840);
    cudaFuncSetAttribute(k_projMM, cudaFuncAttributeMaxDynamicSharedMemorySize, 221184);

    k_prep<<<256, 256>>>(h0, c0);
    k_prepw<<<dim3(16, NTW), 256>>>(wout);
    k_prepg<<<dim3(32, 32, 2), 256>>>(wih0, whh0, wih1, whh1);

    for (int s = 0; s < NSTEP; s++) {
        int p = s & 1;
        k_selembed<<<BB, 512>>>(emb, outp, has_len, s);
        k_gmm<<<dim3(32, KSPL), 256, 163840>>>(0, p);
        k_update2<<<128, 256>>>(bih0, bhh0, 0, p);
        k_gmm<<<dim3(32, KSPL), 256, 163840>>>(1, p);
        k_update2<<<128, 256>>>(bih1, bhh1, 1, p);
        k_projMM<<<NPT, 256, 221184>>>(bout, outp, s, p);
    }
    k_selembed<<<BB, 512>>>(emb, outp, has_len, NSTEP);
}